// round 10
// baseline (speedup 1.0000x reference)
#include <cuda_runtime.h>
#include <cuda_fp16.h>

#define N_NODES 100000
#define N_EDGES 1600000
#define F_IN    128
#define HEADS   8
#define HID     8
#define HC      64
#define NCLS    40
#define NEG_SLOPE 0.2f
#define NB_SCAN 98                     // ceil((N_NODES+1)/1024)

typedef unsigned long long u64;

// ---------------- scratch (static device globals, zero-initialized) ---------
__device__ __align__(16) __half2 g_h1h[(N_NODES + 1) * 32]; // +1 zero row (pad safety)
__device__ __align__(8) __half2 g_e1[N_NODES * HEADS];  // (exp(as1), exp(.2 as1))
__device__ float g_ad1[N_NODES * HEADS];
__device__ __align__(16) __half2 g_h2h[(N_NODES + 1) * 20];
__device__ __half2 g_e2[N_NODES];
__device__ float g_ad2[N_NODES];
__device__ int  g_csr_src[N_EDGES];
__device__ int  g_deg[N_NODES + 1];     // self-cleaning (zeroed by scan_full)
__device__ int  g_off[N_NODES + 1];
__device__ int  g_pos[N_NODES];
__device__ int  g_tile_agg[NB_SCAN];
__device__ int  g_tile_pre[NB_SCAN];
__device__ int  g_arrive;               // self-cleaning
__device__ int  g_epoch;                // bumped by hist each call
__device__ int  g_flag_epoch;           // prefixes-ready flag
__device__ int  g_is64;

// ---------------- packed f32x2 helpers ---------------------------------------
__device__ __forceinline__ u64 pack2(float x, float y) {
    u64 r; asm("mov.b64 %0, {%1, %2};" : "=l"(r) : "f"(x), "f"(y)); return r;
}
__device__ __forceinline__ void fma2(u64& a, u64 b, u64 c) {
    asm("fma.rn.f32x2 %0, %1, %2, %0;" : "+l"(a) : "l"(b), "l"(c));
}
__device__ __forceinline__ float2 unpack2(u64 a) {
    float2 f; asm("mov.b64 {%0, %1}, %2;" : "=f"(f.x), "=f"(f.y) : "l"(a)); return f;
}

// ---------------- hist: per-block probe + dst histogram ----------------------
__global__ void hist_dst(const void* __restrict__ ei) {
    __shared__ int s_is64;
    int tid = threadIdx.x;
    if (tid < 32) {
        const long long* p = (const long long*)ei;
        int bad = 0;
#pragma unroll
        for (int k = 0; k < 8; k++) {
            long long v = p[tid * 8 + k];
            if (v < 0 || v >= (long long)N_NODES) bad = 1;
        }
        unsigned m = __ballot_sync(0xffffffffu, bad);
        if (tid == 0) {
            s_is64 = (m == 0u);
            if (blockIdx.x == 0) { g_is64 = s_is64; g_epoch = g_epoch + 1; }
        }
    }
    __syncthreads();
    unsigned e = blockIdx.x * 256u + tid;
    if (e >= (unsigned)N_EDGES) return;
    int d = s_is64 ? (int)((const long long*)ei)[N_EDGES + e]
                   : ((const int*)ei)[N_EDGES + e];
    atomicAdd(&g_deg[d], 1);
}

// ---------------- single-kernel scan (98 resident blocks, last-block pattern)
__global__ void __launch_bounds__(1024) scan_full() {
    __shared__ int sh[1024];
    __shared__ int s_last;
    __shared__ int s_pref[NB_SCAN];
    int t = threadIdx.x, tile = blockIdx.x;
    int epoch = g_epoch;
    unsigned i = tile * 1024u + t;
    int v = (i <= N_NODES) ? g_deg[i] : 0;
    sh[t] = v; __syncthreads();
#pragma unroll
    for (int off = 1; off < 1024; off <<= 1) {
        int add = (t >= off) ? sh[t - off] : 0;
        __syncthreads();
        sh[t] += add;
        __syncthreads();
    }
    if (t == 0) {
        g_tile_agg[tile] = sh[1023];
        __threadfence();
        int a = atomicAdd(&g_arrive, 1);
        s_last = (a == NB_SCAN - 1);
    }
    __syncthreads();
    if (s_last) {
        if (t < NB_SCAN) s_pref[t] = g_tile_agg[t];
        __syncthreads();
        if (t == 0) {
            int run = 0;
#pragma unroll 2
            for (int j = 0; j < NB_SCAN; j++) { int a = s_pref[j]; s_pref[j] = run; run += a; }
        }
        __syncthreads();
        if (t < NB_SCAN) g_tile_pre[t] = s_pref[t];
        __threadfence();
        if (t == 0) { g_arrive = 0; g_flag_epoch = epoch; }
    } else {
        if (t == 0) {
            while (*(volatile int*)&g_flag_epoch != epoch) { }
        }
        __syncthreads();
        __threadfence();
    }
    int pre = g_tile_pre[tile];
    if (i <= N_NODES) {
        int o = pre + sh[t] - v;   // exclusive
        g_off[i] = o;
        g_deg[i] = 0;              // self-clean for next call
        if (i < N_NODES) g_pos[i] = o;
    }
}

// ---------------- scatter (real edges only) -----------------------------------
__global__ void scatter_csr(const void* __restrict__ ei) {
    unsigned e = blockIdx.x * 256u + threadIdx.x;
    if (e >= (unsigned)N_EDGES) return;
    int s, d;
    if (g_is64) {
        const long long* p = (const long long*)ei;
        s = (int)p[e]; d = (int)p[N_EDGES + e];
    } else {
        const int* p = (const int*)ei;
        s = p[e]; d = p[N_EDGES + e];
    }
    int p2 = atomicAdd(&g_pos[d], 1);
    g_csr_src[p2] = s;
}

// ---------------- layer 1 GEMM + attention logit exp tables -----------------
__global__ void __launch_bounds__(256) gemm1(const float* __restrict__ x,
                                             const float* __restrict__ W,
                                             const float* __restrict__ asrc,
                                             const float* __restrict__ adst) {
    __shared__ float  Ws[F_IN * HC];
    __shared__ float4 xs[8][F_IN];
    __shared__ float  as_s[HC], ad_s[HC];

    int tid = threadIdx.x;
    for (int i = tid; i < F_IN * HC; i += 256) Ws[i] = W[i];
    if (tid < HC) { as_s[tid] = asrc[tid]; ad_s[tid] = adst[tid]; }

    int warp = tid >> 5, lane = tid & 31;
    int n0 = blockIdx.x * 32 + warp * 4;

    for (int k = lane; k < F_IN; k += 32) {
        float4 v;
        v.x = x[(n0 + 0) * F_IN + k];
        v.y = x[(n0 + 1) * F_IN + k];
        v.z = x[(n0 + 2) * F_IN + k];
        v.w = x[(n0 + 3) * F_IN + k];
        xs[warp][k] = v;
    }
    __syncthreads();

    float a00 = 0, a01 = 0, a10 = 0, a11 = 0, a20 = 0, a21 = 0, a30 = 0, a31 = 0;
    const float2* W2p = (const float2*)Ws;
#pragma unroll 8
    for (int k = 0; k < F_IN; k++) {
        float4 xv = xs[warp][k];
        float2 wv = W2p[k * 32 + lane];
        a00 += xv.x * wv.x; a01 += xv.x * wv.y;
        a10 += xv.y * wv.x; a11 += xv.y * wv.y;
        a20 += xv.z * wv.x; a21 += xv.z * wv.y;
        a30 += xv.w * wv.x; a31 += xv.w * wv.y;
    }

    int j0 = lane * 2;
    float asx = as_s[j0], asy = as_s[j0 + 1];
    float adx = ad_s[j0], ady = ad_s[j0 + 1];

#define EMIT(E, A0, A1)                                                          \
    {                                                                            \
        int n = n0 + (E);                                                        \
        g_h1h[n * 32 + lane] = __floats2half2_rn((A0), (A1));                    \
        float ps = (A0) * asx + (A1) * asy;                                      \
        float pd = (A0) * adx + (A1) * ady;                                      \
        ps += __shfl_xor_sync(0xffffffffu, ps, 1);                               \
        ps += __shfl_xor_sync(0xffffffffu, ps, 2);                               \
        pd += __shfl_xor_sync(0xffffffffu, pd, 1);                               \
        pd += __shfl_xor_sync(0xffffffffu, pd, 2);                               \
        if ((lane & 3) == 0) {                                                   \
            int hh = lane >> 2;                                                  \
            g_e1[n * HEADS + hh] = __floats2half2_rn(__expf(ps),                 \
                                                     __expf(0.2f * ps));         \
            g_ad1[n * HEADS + hh] = pd;                                          \
        }                                                                        \
    }
    EMIT(0, a00, a01) EMIT(1, a10, a11) EMIT(2, a20, a21) EMIT(3, a30, a31)
#undef EMIT
}

// ---------------- layer 1 aggregation + fused gemm2 --------------------------
// Warp per node. Lane = slot p=lane>>3 x head q=lane&7. Self loop handled
// inline (slot 0). Accumulation in packed f32x2 (FFMA2).
__global__ void __launch_bounds__(256) edge1_fused(const float* __restrict__ b1,
                                                   const float* __restrict__ W2,
                                                   const float* __restrict__ as2v,
                                                   const float* __restrict__ ad2v) {
    __shared__ float Ws2[HC * NCLS];          // 10 KB
    __shared__ float a2s[NCLS], a2d[NCLS];
    __shared__ float hsm[8][HC];

    int tid = threadIdx.x;
    for (int i = tid; i < HC * NCLS; i += 256) Ws2[i] = W2[i];
    if (tid < NCLS) { a2s[tid] = as2v[tid]; a2d[tid] = ad2v[tid]; }
    __syncthreads();

    int warp = tid >> 5, lane = tid & 31;
    int n = blockIdx.x * 8 + warp;
    if (n >= N_NODES) return;
    int q = lane & 7;                          // head
    int p = lane >> 3;                         // edge slot 0..3

    float ad  = g_ad1[n * 8 + q];
    float epd = __expf(ad);
    float emd = __expf(0.2f * ad);
    float den = 0.f;
    u64 A01 = 0, A23 = 0, A45 = 0, A67 = 0;

#define ACCUM(E, H)                                                              \
    {                                                                            \
        u64 eS = pack2((E), (E));                                                \
        float2 v0 = __half22float2(*(__half2*)&(H).x);                           \
        float2 v1 = __half22float2(*(__half2*)&(H).y);                           \
        float2 v2 = __half22float2(*(__half2*)&(H).z);                           \
        float2 v3 = __half22float2(*(__half2*)&(H).w);                           \
        fma2(A01, pack2(v0.x, v0.y), eS);                                        \
        fma2(A23, pack2(v1.x, v1.y), eS);                                        \
        fma2(A45, pack2(v2.x, v2.y), eS);                                        \
        fma2(A67, pack2(v3.x, v3.y), eS);                                        \
        den += (E);                                                              \
    }

    // self loop (slot 0 only, so reduce counts it once)
    if (p == 0) {
        __half2 es = g_e1[n * 8 + q];
        uint4 h = *(const uint4*)(g_h1h + n * 32 + q * 4);
        float2 ef = __half22float2(es);
        float pe = ef.x * epd;
        float e = pe > 1.f ? pe : ef.y * emd;
        ACCUM(e, h)
    }

    int k = g_off[n], end = g_off[n + 1];
    while (k < end) {
        int cnt = min(32, end - k);
        int sv = (lane < cnt) ? g_csr_src[k + lane] : 0;
        int j = 0;
        for (; j + 16 <= cnt; j += 16) {      // 4 edges per lane, 16 per warp
            int s[4]; __half2 es[4]; uint4 h[4];
#pragma unroll
            for (int u = 0; u < 4; u++) s[u] = __shfl_sync(0xffffffffu, sv, j + 4 * u + p);
#pragma unroll
            for (int u = 0; u < 4; u++) {
                es[u] = g_e1[s[u] * 8 + q];
                h[u]  = *(const uint4*)(g_h1h + s[u] * 32 + q * 4);
            }
#pragma unroll
            for (int u = 0; u < 4; u++) {
                float2 ef = __half22float2(es[u]);
                float pe = ef.x * epd;
                float e = pe > 1.f ? pe : ef.y * emd;
                ACCUM(e, h[u])
            }
        }
        for (; j < cnt; j += 4) {             // leftover: up to 4 edges
            int je = j + p;
            bool valid = je < cnt;
            int s = __shfl_sync(0xffffffffu, sv, je & 31);
            __half2 es = g_e1[s * 8 + q];
            uint4 h = *(const uint4*)(g_h1h + s * 32 + q * 4);
            float2 ef = __half22float2(es);
            float pe = ef.x * epd;
            float e = valid ? (pe > 1.f ? pe : ef.y * emd) : 0.f;
            ACCUM(e, h)
        }
        k += cnt;
    }
#undef ACCUM

    float2 f01 = unpack2(A01), f23 = unpack2(A23), f45 = unpack2(A45), f67 = unpack2(A67);
    float a0 = f01.x, a1 = f01.y, a2 = f23.x, a3 = f23.y,
          a4 = f45.x, a5 = f45.y, a6 = f67.x, a7 = f67.y;

#define RED(X) X += __shfl_xor_sync(0xffffffffu, X, 8); X += __shfl_xor_sync(0xffffffffu, X, 16);
    RED(den) RED(a0) RED(a1) RED(a2) RED(a3) RED(a4) RED(a5) RED(a6) RED(a7)
#undef RED

    if (p == 0) {
        int c0 = q * 8;
        float4 ba = *(const float4*)(b1 + c0);
        float4 bb = *(const float4*)(b1 + c0 + 4);
        float inv = 1.f / (den + 1e-16f);
        hsm[warp][c0]     = fmaxf(a0 * inv + ba.x, 0.f);
        hsm[warp][c0 + 1] = fmaxf(a1 * inv + ba.y, 0.f);
        hsm[warp][c0 + 2] = fmaxf(a2 * inv + ba.z, 0.f);
        hsm[warp][c0 + 3] = fmaxf(a3 * inv + ba.w, 0.f);
        hsm[warp][c0 + 4] = fmaxf(a4 * inv + bb.x, 0.f);
        hsm[warp][c0 + 5] = fmaxf(a5 * inv + bb.y, 0.f);
        hsm[warp][c0 + 6] = fmaxf(a6 * inv + bb.z, 0.f);
        hsm[warp][c0 + 7] = fmaxf(a7 * inv + bb.w, 0.f);
    }
    __syncwarp();

    // ---- fused layer-2 GEMM ----
    float acc0 = 0.f, acc1 = 0.f;
    int l8 = 32 + (lane & 7);
#pragma unroll 8
    for (int w = 0; w < HC; w++) {
        float hv = hsm[warp][w];
        acc0 += hv * Ws2[w * NCLS + lane];
        acc1 += hv * Ws2[w * NCLS + l8];
    }

    __half* h2p = (__half*)g_h2h;
    h2p[n * NCLS + lane] = __float2half_rn(acc0);
    if (lane < 8) h2p[n * NCLS + 32 + lane] = __float2half_rn(acc1);

    float ps = acc0 * a2s[lane] + (lane < 8 ? acc1 * a2s[32 + lane] : 0.f);
    float pd = acc0 * a2d[lane] + (lane < 8 ? acc1 * a2d[32 + lane] : 0.f);
#pragma unroll
    for (int o = 16; o; o >>= 1) {
        ps += __shfl_xor_sync(0xffffffffu, ps, o);
        pd += __shfl_xor_sync(0xffffffffu, pd, o);
    }
    if (lane == 0) {
        g_e2[n] = __floats2half2_rn(__expf(ps), __expf(0.2f * ps));
        g_ad2[n] = pd;
    }
}

// ---------------- layer 2 CSR aggregation ------------------------------------
// 6 groups of 5 lanes; lane t owns classes [8t,8t+8). Self loop in group 0.
__global__ void __launch_bounds__(256) edge_csr2(float* __restrict__ out,
                                                 const float* __restrict__ b2) {
    int warp = (blockIdx.x * 256 + threadIdx.x) >> 5;
    int lane = threadIdx.x & 31;
    if (warp >= N_NODES) return;
    int n = warp;
    int g = lane / 5;
    int t = lane - g * 5;
    bool live = g < 6;
    int ti = live ? t : 0;

    float ad  = g_ad2[n];
    float epd = __expf(ad);
    float emd = __expf(0.2f * ad);
    float den = 0.f;
    u64 A01 = 0, A23 = 0, A45 = 0, A67 = 0;

#define ACCUM(E, H)                                                              \
    {                                                                            \
        u64 eS = pack2((E), (E));                                                \
        float2 v0 = __half22float2(*(__half2*)&(H).x);                           \
        float2 v1 = __half22float2(*(__half2*)&(H).y);                           \
        float2 v2 = __half22float2(*(__half2*)&(H).z);                           \
        float2 v3 = __half22float2(*(__half2*)&(H).w);                           \
        fma2(A01, pack2(v0.x, v0.y), eS);                                        \
        fma2(A23, pack2(v1.x, v1.y), eS);                                        \
        fma2(A45, pack2(v2.x, v2.y), eS);                                        \
        fma2(A67, pack2(v3.x, v3.y), eS);                                        \
        den += (E);                                                              \
    }

    // self loop (group 0)
    if (g == 0) {
        __half2 es = g_e2[n];
        uint4 h = *(const uint4*)((const uint4*)g_h2h + n * 5 + ti);
        float2 ef = __half22float2(es);
        float pe = ef.x * epd;
        float e = pe > 1.f ? pe : ef.y * emd;
        ACCUM(e, h)
    }

    int k = g_off[n], end = g_off[n + 1];
    while (k < end) {
        int cnt = min(32, end - k);
        int sv = (lane < cnt) ? g_csr_src[k + lane] : 0;
        int j = 0;
        for (; j + 12 <= cnt; j += 12) {      // 2 edges per group, 12 per warp
            int s0 = __shfl_sync(0xffffffffu, sv, (j + g) & 31);
            int s1 = __shfl_sync(0xffffffffu, sv, (j + 6 + g) & 31);
            __half2 es0 = g_e2[s0];
            __half2 es1 = g_e2[s1];
            uint4 h0 = *(const uint4*)((const uint4*)g_h2h + s0 * 5 + ti);
            uint4 h1 = *(const uint4*)((const uint4*)g_h2h + s1 * 5 + ti);
            float2 ef0 = __half22float2(es0);
            float2 ef1 = __half22float2(es1);
            float pe0 = ef0.x * epd;
            float pe1 = ef1.x * epd;
            float e0 = live ? (pe0 > 1.f ? pe0 : ef0.y * emd) : 0.f;
            float e1 = live ? (pe1 > 1.f ? pe1 : ef1.y * emd) : 0.f;
            ACCUM(e0, h0)
            ACCUM(e1, h1)
        }
        for (; j < cnt; j += 6) {             // leftover: up to 6 edges
            int je = j + g;
            bool valid = live && (je < cnt);
            int s = __shfl_sync(0xffffffffu, sv, je & 31);
            __half2 es = g_e2[s];
            uint4 h = *(const uint4*)((const uint4*)g_h2h + s * 5 + ti);
            float2 ef = __half22float2(es);
            float pe = ef.x * epd;
            float e = valid ? (pe > 1.f ? pe : ef.y * emd) : 0.f;
            ACCUM(e, h)
        }
        k += cnt;
    }
#undef ACCUM

    float2 f01 = unpack2(A01), f23 = unpack2(A23), f45 = unpack2(A45), f67 = unpack2(A67);
    float a0 = f01.x, a1 = f01.y, a2 = f23.x, a3 = f23.y,
          a4 = f45.x, a5 = f45.y, a6 = f67.x, a7 = f67.y;

#define RED(X)                                                                   \
    {                                                                            \
        float w = __shfl_sync(0xffffffffu, X, (lane + 15) & 31); X += w;         \
        float u = __shfl_sync(0xffffffffu, X, (lane + 5) & 31);                  \
        float v = __shfl_sync(0xffffffffu, X, (lane + 10) & 31);                 \
        X += u + v;                                                              \
    }
    RED(den) RED(a0) RED(a1) RED(a2) RED(a3) RED(a4) RED(a5) RED(a6) RED(a7)
#undef RED

    if (lane < 5) {
        int c0 = lane * 8;
        float4 ba = *(const float4*)(b2 + c0);
        float4 bb = *(const float4*)(b2 + c0 + 4);
        float inv = 1.f / (den + 1e-16f);
        float4 r0, r1;
        r0.x = a0 * inv + ba.x; r0.y = a1 * inv + ba.y;
        r0.z = a2 * inv + ba.z; r0.w = a3 * inv + ba.w;
        r1.x = a4 * inv + bb.x; r1.y = a5 * inv + bb.y;
        r1.z = a6 * inv + bb.z; r1.w = a7 * inv + bb.w;
        *(float4*)(out + n * NCLS + c0)     = r0;
        *(float4*)(out + n * NCLS + c0 + 4) = r1;
    }
}

// ---------------- launch -----------------------------------------------------
extern "C" void kernel_launch(void* const* d_in, const int* in_sizes, int n_in,
                              void* d_out, int out_size) {
    const float* x   = (const float*)d_in[0];
    const void*  ei  = d_in[1];
    const float* W1  = (const float*)d_in[2];
    const float* as1 = (const float*)d_in[3];
    const float* ad1 = (const float*)d_in[4];
    const float* b1  = (const float*)d_in[5];
    const float* W2  = (const float*)d_in[6];
    const float* as2 = (const float*)d_in[7];
    const float* ad2 = (const float*)d_in[8];
    const float* b2  = (const float*)d_in[9];
    float*       out = (float*)d_out;

    // fork: CSR build on side stream, gemm1 concurrently on main stream
    cudaStream_t s1;
    cudaStreamCreateWithFlags(&s1, cudaStreamNonBlocking);
    cudaEvent_t ev0, ev1;
    cudaEventCreateWithFlags(&ev0, cudaEventDisableTiming);
    cudaEventCreateWithFlags(&ev1, cudaEventDisableTiming);

    cudaEventRecord(ev0, 0);
    cudaStreamWaitEvent(s1, ev0, 0);

    // ---- CSR build (side stream): 3 kernels ----
    hist_dst<<<(N_EDGES + 255) / 256, 256, 0, s1>>>(ei);
    scan_full<<<NB_SCAN, 1024, 0, s1>>>();
    scatter_csr<<<(N_EDGES + 255) / 256, 256, 0, s1>>>(ei);
    cudaEventRecord(ev1, s1);

    // ---- layer 1 GEMM (main stream, overlapped) ----
    gemm1<<<N_NODES / 32, 256>>>(x, W1, as1, ad1);

    // join
    cudaStreamWaitEvent(0, ev1, 0);

    // ---- layer 1 aggregation + fused layer-2 GEMM ----
    edge1_fused<<<(N_NODES + 7) / 8, 256>>>(b1, W2, as2, ad2);

    // ---- layer 2 ----
    edge_csr2<<<(N_NODES * 32 + 255) / 256, 256>>>(out, b2);

    cudaEventDestroy(ev0);
    cudaEventDestroy(ev1);
    cudaStreamDestroy(s1);
}

// round 11
// speedup vs baseline: 1.0800x; 1.0800x over previous
#include <cuda_runtime.h>
#include <cuda_fp16.h>

#define N_NODES 100000
#define N_EDGES 1600000
#define TOT_E   (N_EDGES + N_NODES)   // edges + self loops
#define F_IN    128
#define HEADS   8
#define HID     8
#define HC      64
#define NCLS    40
#define NEG_SLOPE 0.2f
#define NB_SCAN 98                     // ceil((N_NODES+1)/1024)

typedef unsigned long long u64;

// ---------------- scratch (static device globals, zero-initialized) ---------
__device__ __align__(16) __half2 g_h1h[N_NODES * 32];   // layer1 features, fp16 pairs
__device__ __align__(8) __half2 g_e1[N_NODES * HEADS];  // (exp(as1), exp(.2 as1))
__device__ float g_ad1[N_NODES * HEADS];
__device__ __align__(16) __half2 g_h2h[N_NODES * 20];   // layer2 features, fp16 pairs
__device__ __half2 g_e2[N_NODES];
__device__ float g_ad2[N_NODES];
__device__ int  g_csr_src[TOT_E];
__device__ int  g_deg[N_NODES + 1];     // self-cleaning (zeroed in fixup)
__device__ int  g_off[N_NODES + 1];
__device__ int  g_pos[N_NODES];
__device__ int  g_bsum[NB_SCAN];
__device__ int  g_is64;

// ---------------- packed f32x2 helpers ---------------------------------------
__device__ __forceinline__ u64 pack2(float x, float y) {
    u64 r; asm("mov.b64 %0, {%1, %2};" : "=l"(r) : "f"(x), "f"(y)); return r;
}
__device__ __forceinline__ void fma2(u64& a, u64 b, u64 c) {
    asm("fma.rn.f32x2 %0, %1, %2, %0;" : "+l"(a) : "l"(b), "l"(c));
}
__device__ __forceinline__ float2 unpack2(u64 a) {
    float2 f; asm("mov.b64 {%0, %1}, %2;" : "=f"(f.x), "=f"(f.y) : "l"(a)); return f;
}

__device__ __forceinline__ float lrelu(float x) { return x > 0.f ? x : NEG_SLOPE * x; }

// ---------------- hist (per-block dtype probe merged in) ---------------------
__global__ void hist_dst(const void* __restrict__ ei) {
    __shared__ int s_is64;
    int tid = threadIdx.x;
    if (tid < 32) {
        const long long* p = (const long long*)ei;
        int bad = 0;
#pragma unroll
        for (int k = 0; k < 8; k++) {
            long long v = p[tid * 8 + k];
            if (v < 0 || v >= (long long)N_NODES) bad = 1;
        }
        unsigned m = __ballot_sync(0xffffffffu, bad);
        if (tid == 0) {
            s_is64 = (m == 0u);
            if (blockIdx.x == 0) g_is64 = s_is64;
        }
    }
    __syncthreads();
    unsigned e = blockIdx.x * 256u + tid;
    if (e >= (unsigned)TOT_E) return;
    int d;
    if (e < (unsigned)N_EDGES) {
        d = s_is64 ? (int)((const long long*)ei)[N_EDGES + e]
                   : ((const int*)ei)[N_EDGES + e];
    } else {
        d = (int)(e - (unsigned)N_EDGES);
    }
    atomicAdd(&g_deg[d], 1);
}

__global__ void __launch_bounds__(1024) scan_blocks() {
    __shared__ int sh[1024];
    int t = threadIdx.x;
    unsigned i = blockIdx.x * 1024u + t;
    int v = (i <= N_NODES) ? g_deg[i] : 0;
    sh[t] = v; __syncthreads();
#pragma unroll
    for (int off = 1; off < 1024; off <<= 1) {
        int add = (t >= off) ? sh[t - off] : 0;
        __syncthreads();
        sh[t] += add;
        __syncthreads();
    }
    if (i <= N_NODES) g_off[i] = sh[t] - v;
    if (t == 1023) g_bsum[blockIdx.x] = sh[t];
}

__global__ void __launch_bounds__(256) fixup_offsets() {
    __shared__ int sb[128];
    int t = threadIdx.x;
    if (t < 128) sb[t] = (t < NB_SCAN) ? g_bsum[t] : 0;
    __syncthreads();
#pragma unroll
    for (int off = 1; off < 128; off <<= 1) {
        int add = (t < 128 && t >= off) ? sb[t - off] : 0;
        __syncthreads();
        if (t < 128) sb[t] += add;
        __syncthreads();
    }
    unsigned i = blockIdx.x * 256u + t;
    if (i > N_NODES) return;
    unsigned b = i >> 10;
    int pre = (b == 0) ? 0 : sb[b - 1];       // exclusive
    int o = g_off[i] + pre;
    g_off[i] = o;
    g_deg[i] = 0;                             // self-clean for next call
    if (i < N_NODES) g_pos[i] = o;
}

__global__ void scatter_csr(const void* __restrict__ ei) {
    unsigned e = blockIdx.x * 256u + threadIdx.x;
    if (e >= (unsigned)TOT_E) return;
    int s, d;
    if (e < (unsigned)N_EDGES) {
        if (g_is64) {
            const long long* p = (const long long*)ei;
            s = (int)p[e]; d = (int)p[N_EDGES + e];
        } else {
            const int* p = (const int*)ei;
            s = p[e]; d = p[N_EDGES + e];
        }
    } else {
        s = d = (int)(e - (unsigned)N_EDGES);
    }
    int p = atomicAdd(&g_pos[d], 1);
    g_csr_src[p] = s;
}

// ---------------- layer 1 GEMM: 8 nodes/warp, f32x2 accumulation -------------
// Warp handles 8 nodes; lane owns cols 2l, 2l+1. Per k: 2 broadcast LDS.128
// (x values for 8 nodes) + 1 LDS.64 (W pair) -> 8 FFMA2.
__global__ void __launch_bounds__(256) gemm1(const float* __restrict__ x,
                                             const float* __restrict__ W,
                                             const float* __restrict__ asrc,
                                             const float* __restrict__ adst) {
    __shared__ float Ws[F_IN * HC];           // 32 KB
    __shared__ float xs[8][F_IN * 8];         // 32 KB: [warp][k*8 + node]
    __shared__ float as_s[HC], ad_s[HC];

    int tid = threadIdx.x;
    for (int i = tid; i < F_IN * HC; i += 256) Ws[i] = W[i];
    if (tid < HC) { as_s[tid] = asrc[tid]; ad_s[tid] = adst[tid]; }

    int warp = tid >> 5, lane = tid & 31;
    int n0 = blockIdx.x * 64 + warp * 8;      // grid = 1563, last block partial

#pragma unroll
    for (int u = 0; u < 8; u++) {
        int n = n0 + u; if (n >= N_NODES) n = N_NODES - 1;   // clamp (dup read ok)
        const float* xr = x + (size_t)n * F_IN;
#pragma unroll
        for (int c = 0; c < 4; c++) {
            int k = lane + c * 32;
            xs[warp][k * 8 + u] = xr[k];
        }
    }
    __syncthreads();

    const float2* W2p = (const float2*)Ws;
    u64 acc[8];
#pragma unroll
    for (int u = 0; u < 8; u++) acc[u] = 0;

#pragma unroll 4
    for (int k = 0; k < F_IN; k++) {
        float4 xa = *(const float4*)&xs[warp][k * 8];
        float4 xb = *(const float4*)&xs[warp][k * 8 + 4];
        float2 wv = W2p[k * 32 + lane];
        u64 wp = pack2(wv.x, wv.y);
        fma2(acc[0], pack2(xa.x, xa.x), wp);
        fma2(acc[1], pack2(xa.y, xa.y), wp);
        fma2(acc[2], pack2(xa.z, xa.z), wp);
        fma2(acc[3], pack2(xa.w, xa.w), wp);
        fma2(acc[4], pack2(xb.x, xb.x), wp);
        fma2(acc[5], pack2(xb.y, xb.y), wp);
        fma2(acc[6], pack2(xb.z, xb.z), wp);
        fma2(acc[7], pack2(xb.w, xb.w), wp);
    }

    int j0 = lane * 2;
    float asx = as_s[j0], asy = as_s[j0 + 1];
    float adx = ad_s[j0], ady = ad_s[j0 + 1];

#pragma unroll
    for (int u = 0; u < 8; u++) {
        int n = n0 + u;
        float2 f = unpack2(acc[u]);
        float A0 = f.x, A1 = f.y;
        float ps = A0 * asx + A1 * asy;
        float pd = A0 * adx + A1 * ady;
        ps += __shfl_xor_sync(0xffffffffu, ps, 1);
        ps += __shfl_xor_sync(0xffffffffu, ps, 2);
        pd += __shfl_xor_sync(0xffffffffu, pd, 1);
        pd += __shfl_xor_sync(0xffffffffu, pd, 2);
        if (n < N_NODES) {
            g_h1h[n * 32 + lane] = __floats2half2_rn(A0, A1);
            if ((lane & 3) == 0) {
                int hh = lane >> 2;
                g_e1[n * HEADS + hh] = __floats2half2_rn(__expf(ps), __expf(0.2f * ps));
                g_ad1[n * HEADS + hh] = pd;
            }
        }
    }
}

// ---------------- layer 1 aggregation (table-based exp) + fused gemm2 -------
// Warp per node. Lane = slot p=lane>>3 x head q=lane&7.
__global__ void __launch_bounds__(256) edge1_fused(const float* __restrict__ b1,
                                                   const float* __restrict__ W2,
                                                   const float* __restrict__ as2v,
                                                   const float* __restrict__ ad2v) {
    __shared__ float Ws2[HC * NCLS];          // 10 KB
    __shared__ float a2s[NCLS], a2d[NCLS];
    __shared__ float hs[8][HC];

    int tid = threadIdx.x;
    for (int i = tid; i < HC * NCLS; i += 256) Ws2[i] = W2[i];
    if (tid < NCLS) { a2s[tid] = as2v[tid]; a2d[tid] = ad2v[tid]; }
    __syncthreads();

    int warp = tid >> 5, lane = tid & 31;
    int n = blockIdx.x * 8 + warp;
    if (n >= N_NODES) return;
    int q = lane & 7;                          // head
    int p = lane >> 3;                         // edge slot 0..3

    float ad  = g_ad1[n * 8 + q];
    float epd = __expf(ad);
    float emd = __expf(0.2f * ad);
    float den = 0.f;
    float a0 = 0.f, a1 = 0.f, a2 = 0.f, a3 = 0.f,
          a4 = 0.f, a5 = 0.f, a6 = 0.f, a7 = 0.f;

#define ACCUM(E, H)                                                              \
    {                                                                            \
        float2 v0 = __half22float2(*(__half2*)&(H).x);                           \
        float2 v1 = __half22float2(*(__half2*)&(H).y);                           \
        float2 v2 = __half22float2(*(__half2*)&(H).z);                           \
        float2 v3 = __half22float2(*(__half2*)&(H).w);                           \
        a0 += (E) * v0.x; a1 += (E) * v0.y; a2 += (E) * v1.x; a3 += (E) * v1.y;  \
        a4 += (E) * v2.x; a5 += (E) * v2.y; a6 += (E) * v3.x; a7 += (E) * v3.y;  \
    }

    int k = g_off[n], end = g_off[n + 1];
    while (k < end) {
        int cnt = min(32, end - k);
        int sv = (lane < cnt) ? g_csr_src[k + lane] : 0;
        int j = 0;
        for (; j + 16 <= cnt; j += 16) {      // 4 edges per lane, 16 per warp
            int s[4]; __half2 es[4]; uint4 h[4];
#pragma unroll
            for (int u = 0; u < 4; u++) s[u] = __shfl_sync(0xffffffffu, sv, j + 4 * u + p);
#pragma unroll
            for (int u = 0; u < 4; u++) {
                es[u] = g_e1[s[u] * 8 + q];
                h[u]  = *(const uint4*)(g_h1h + s[u] * 32 + q * 4);
            }
#pragma unroll
            for (int u = 0; u < 4; u++) {
                float2 ef = __half22float2(es[u]);
                float pe = ef.x * epd;
                float e = pe > 1.f ? pe : ef.y * emd;
                den += e;
                ACCUM(e, h[u])
            }
        }
        for (; j < cnt; j += 4) {             // leftover: up to 4 edges
            int je = j + p;
            bool valid = je < cnt;
            int s = __shfl_sync(0xffffffffu, sv, je & 31);
            __half2 es = g_e1[s * 8 + q];
            uint4 h = *(const uint4*)(g_h1h + s * 32 + q * 4);
            float2 ef = __half22float2(es);
            float pe = ef.x * epd;
            float e = valid ? (pe > 1.f ? pe : ef.y * emd) : 0.f;
            den += e;
            ACCUM(e, h)
        }
        k += cnt;
    }
#undef ACCUM

#define RED(X) X += __shfl_xor_sync(0xffffffffu, X, 8); X += __shfl_xor_sync(0xffffffffu, X, 16);
    RED(den) RED(a0) RED(a1) RED(a2) RED(a3) RED(a4) RED(a5) RED(a6) RED(a7)
#undef RED

    if (p == 0) {
        int c0 = q * 8;
        float4 ba = *(const float4*)(b1 + c0);
        float4 bb = *(const float4*)(b1 + c0 + 4);
        float inv = 1.f / (den + 1e-16f);
        hs[warp][c0]     = fmaxf(a0 * inv + ba.x, 0.f);
        hs[warp][c0 + 1] = fmaxf(a1 * inv + ba.y, 0.f);
        hs[warp][c0 + 2] = fmaxf(a2 * inv + ba.z, 0.f);
        hs[warp][c0 + 3] = fmaxf(a3 * inv + ba.w, 0.f);
        hs[warp][c0 + 4] = fmaxf(a4 * inv + bb.x, 0.f);
        hs[warp][c0 + 5] = fmaxf(a5 * inv + bb.y, 0.f);
        hs[warp][c0 + 6] = fmaxf(a6 * inv + bb.z, 0.f);
        hs[warp][c0 + 7] = fmaxf(a7 * inv + bb.w, 0.f);
    }
    __syncwarp();

    // ---- fused layer-2 GEMM ----
    float acc0 = 0.f, acc1 = 0.f;
    int l8 = 32 + (lane & 7);
#pragma unroll 8
    for (int w = 0; w < HC; w++) {
        float hv = hs[warp][w];
        acc0 += hv * Ws2[w * NCLS + lane];
        acc1 += hv * Ws2[w * NCLS + l8];
    }

    __half* h2p = (__half*)g_h2h;
    h2p[n * NCLS + lane] = __float2half_rn(acc0);
    if (lane < 8) h2p[n * NCLS + 32 + lane] = __float2half_rn(acc1);

    float ps = acc0 * a2s[lane] + (lane < 8 ? acc1 * a2s[32 + lane] : 0.f);
    float pd = acc0 * a2d[lane] + (lane < 8 ? acc1 * a2d[32 + lane] : 0.f);
#pragma unroll
    for (int o = 16; o; o >>= 1) {
        ps += __shfl_xor_sync(0xffffffffu, ps, o);
        pd += __shfl_xor_sync(0xffffffffu, pd, o);
    }
    if (lane == 0) {
        g_e2[n] = __floats2half2_rn(__expf(ps), __expf(0.2f * ps));
        g_ad2[n] = pd;
    }
}

// ---------------- layer 2 CSR aggregation (table-based exp) ------------------
__global__ void __launch_bounds__(256) edge_csr2(float* __restrict__ out,
                                                 const float* __restrict__ b2) {
    int warp = (blockIdx.x * 256 + threadIdx.x) >> 5;
    int lane = threadIdx.x & 31;
    if (warp >= N_NODES) return;
    int n = warp;
    int g = lane / 5;
    int t = lane - g * 5;
    bool live = g < 6;
    int ti = live ? t : 0;

    float ad  = g_ad2[n];
    float epd = __expf(ad);
    float emd = __expf(0.2f * ad);
    float den = 0.f;
    float a0 = 0.f, a1 = 0.f, a2 = 0.f, a3 = 0.f,
          a4 = 0.f, a5 = 0.f, a6 = 0.f, a7 = 0.f;

#define ACCUM(E, H)                                                              \
    {                                                                            \
        float2 v0 = __half22float2(*(__half2*)&(H).x);                           \
        float2 v1 = __half22float2(*(__half2*)&(H).y);                           \
        float2 v2 = __half22float2(*(__half2*)&(H).z);                           \
        float2 v3 = __half22float2(*(__half2*)&(H).w);                           \
        a0 += (E) * v0.x; a1 += (E) * v0.y; a2 += (E) * v1.x; a3 += (E) * v1.y;  \
        a4 += (E) * v2.x; a5 += (E) * v2.y; a6 += (E) * v3.x; a7 += (E) * v3.y;  \
    }

    int k = g_off[n], end = g_off[n + 1];
    while (k < end) {
        int cnt = min(32, end - k);
        int sv = (lane < cnt) ? g_csr_src[k + lane] : 0;
        int j = 0;
        for (; j + 12 <= cnt; j += 12) {      // 2 edges per group, 12 per warp
            int s0 = __shfl_sync(0xffffffffu, sv, (j + g) & 31);
            int s1 = __shfl_sync(0xffffffffu, sv, (j + 6 + g) & 31);
            __half2 es0 = g_e2[s0];
            __half2 es1 = g_e2[s1];
            uint4 h0 = *(const uint4*)((const uint4*)g_h2h + s0 * 5 + ti);
            uint4 h1 = *(const uint4*)((const uint4*)g_h2h + s1 * 5 + ti);
            float2 ef0 = __half22float2(es0);
            float2 ef1 = __half22float2(es1);
            float pe0 = ef0.x * epd;
            float pe1 = ef1.x * epd;
            float e0 = live ? (pe0 > 1.f ? pe0 : ef0.y * emd) : 0.f;
            float e1 = live ? (pe1 > 1.f ? pe1 : ef1.y * emd) : 0.f;
            den += e0 + e1;
            ACCUM(e0, h0)
            ACCUM(e1, h1)
        }
        for (; j < cnt; j += 6) {             // leftover: up to 6 edges
            int je = j + g;
            bool valid = live && (je < cnt);
            int s = __shfl_sync(0xffffffffu, sv, je & 31);
            __half2 es = g_e2[s];
            uint4 h = *(const uint4*)((const uint4*)g_h2h + s * 5 + ti);
            float2 ef = __half22float2(es);
            float pe = ef.x * epd;
            float e = valid ? (pe > 1.f ? pe : ef.y * emd) : 0.f;
            den += e;
            ACCUM(e, h)
        }
        k += cnt;
    }
#undef ACCUM

#define RED(X)                                                                   \
    {                                                                            \
        float w = __shfl_sync(0xffffffffu, X, (lane + 15) & 31); X += w;         \
        float u = __shfl_sync(0xffffffffu, X, (lane + 5) & 31);                  \
        float v = __shfl_sync(0xffffffffu, X, (lane + 10) & 31);                 \
        X += u + v;                                                              \
    }
    RED(den) RED(a0) RED(a1) RED(a2) RED(a3) RED(a4) RED(a5) RED(a6) RED(a7)
#undef RED

    if (lane < 5) {
        int c0 = lane * 8;
        float4 ba = *(const float4*)(b2 + c0);
        float4 bb = *(const float4*)(b2 + c0 + 4);
        float inv = 1.f / (den + 1e-16f);
        float4 r0, r1;
        r0.x = a0 * inv + ba.x; r0.y = a1 * inv + ba.y;
        r0.z = a2 * inv + ba.z; r0.w = a3 * inv + ba.w;
        r1.x = a4 * inv + bb.x; r1.y = a5 * inv + bb.y;
        r1.z = a6 * inv + bb.z; r1.w = a7 * inv + bb.w;
        *(float4*)(out + n * NCLS + c0)     = r0;
        *(float4*)(out + n * NCLS + c0 + 4) = r1;
    }
}

// ---------------- launch -----------------------------------------------------
extern "C" void kernel_launch(void* const* d_in, const int* in_sizes, int n_in,
                              void* d_out, int out_size) {
    const float* x   = (const float*)d_in[0];
    const void*  ei  = d_in[1];
    const float* W1  = (const float*)d_in[2];
    const float* as1 = (const float*)d_in[3];
    const float* ad1 = (const float*)d_in[4];
    const float* b1  = (const float*)d_in[5];
    const float* W2  = (const float*)d_in[6];
    const float* as2 = (const float*)d_in[7];
    const float* ad2 = (const float*)d_in[8];
    const float* b2  = (const float*)d_in[9];
    float*       out = (float*)d_out;

    // fork: CSR build on side stream, gemm1 concurrently on main stream
    cudaStream_t s1;
    cudaStreamCreateWithFlags(&s1, cudaStreamNonBlocking);
    cudaEvent_t ev0, ev1;
    cudaEventCreateWithFlags(&ev0, cudaEventDisableTiming);
    cudaEventCreateWithFlags(&ev1, cudaEventDisableTiming);

    cudaEventRecord(ev0, 0);
    cudaStreamWaitEvent(s1, ev0, 0);

    // ---- CSR build (side stream): 4 kernels ----
    hist_dst<<<((unsigned)TOT_E + 255) / 256, 256, 0, s1>>>(ei);
    scan_blocks<<<NB_SCAN, 1024, 0, s1>>>();
    fixup_offsets<<<(N_NODES + 256) / 256, 256, 0, s1>>>();
    scatter_csr<<<((unsigned)TOT_E + 255) / 256, 256, 0, s1>>>(ei);
    cudaEventRecord(ev1, s1);

    // ---- layer 1 GEMM (main stream, overlapped) ----
    gemm1<<<(N_NODES + 63) / 64, 256>>>(x, W1, as1, ad1);

    // join
    cudaStreamWaitEvent(0, ev1, 0);

    // ---- layer 1 aggregation + fused layer-2 GEMM ----
    edge1_fused<<<(N_NODES + 7) / 8, 256>>>(b1, W2, as2, ad2);

    // ---- layer 2 ----
    edge_csr2<<<(N_NODES * 32 + 255) / 256, 256>>>(out, b2);

    cudaEventDestroy(ev0);
    cudaEventDestroy(ev1);
    cudaStreamDestroy(s1);
}

// round 12
// speedup vs baseline: 1.1083x; 1.0262x over previous
#include <cuda_runtime.h>
#include <cuda_fp16.h>

#define N_NODES 100000
#define N_EDGES 1600000
#define TOT_E   (N_EDGES + N_NODES)   // edges + self loops
#define F_IN    128
#define HEADS   8
#define HID     8
#define HC      64
#define NCLS    40
#define NEG_SLOPE 0.2f
#define NB_SCAN 98                     // ceil((N_NODES+1)/1024)

typedef unsigned long long u64;

// ---------------- scratch (static device globals, zero-initialized) ---------
__device__ __align__(16) __half2 g_h1h[N_NODES * 32];   // layer1 features, fp16 pairs
__device__ __align__(8) __half2 g_e1[N_NODES * HEADS];  // (exp(as1), exp(.2 as1))
__device__ float g_ad1[N_NODES * HEADS];
__device__ __align__(16) __half2 g_h2h[N_NODES * 20];   // layer2 features, fp16 pairs
__device__ __half2 g_e2[N_NODES];
__device__ float g_ad2[N_NODES];
__device__ int  g_csr_src[TOT_E];
__device__ int  g_rank[TOT_E];          // per-edge rank within its destination
__device__ int  g_deg[N_NODES + 1];     // self-cleaning (zeroed in fixup)
__device__ int  g_off[N_NODES + 1];
__device__ int  g_bsum[NB_SCAN];
__device__ int  g_is64;

// ---------------- packed f32x2 helpers ---------------------------------------
__device__ __forceinline__ u64 pack2(float x, float y) {
    u64 r; asm("mov.b64 %0, {%1, %2};" : "=l"(r) : "f"(x), "f"(y)); return r;
}
__device__ __forceinline__ void fma2(u64& a, u64 b, u64 c) {
    asm("fma.rn.f32x2 %0, %1, %2, %0;" : "+l"(a) : "l"(b), "l"(c));
}
__device__ __forceinline__ float2 unpack2(u64 a) {
    float2 f; asm("mov.b64 {%0, %1}, %2;" : "=f"(f.x), "=f"(f.y) : "l"(a)); return f;
}

// ---------------- hist (probe + histogram + rank capture) --------------------
__global__ void hist_dst(const void* __restrict__ ei) {
    __shared__ int s_is64;
    int tid = threadIdx.x;
    if (tid < 32) {
        const long long* p = (const long long*)ei;
        int bad = 0;
#pragma unroll
        for (int k = 0; k < 8; k++) {
            long long v = p[tid * 8 + k];
            if (v < 0 || v >= (long long)N_NODES) bad = 1;
        }
        unsigned m = __ballot_sync(0xffffffffu, bad);
        if (tid == 0) {
            s_is64 = (m == 0u);
            if (blockIdx.x == 0) g_is64 = s_is64;
        }
    }
    __syncthreads();
    unsigned e = blockIdx.x * 256u + tid;
    if (e >= (unsigned)TOT_E) return;
    int d;
    if (e < (unsigned)N_EDGES) {
        d = s_is64 ? (int)((const long long*)ei)[N_EDGES + e]
                   : ((const int*)ei)[N_EDGES + e];
    } else {
        d = (int)(e - (unsigned)N_EDGES);
    }
    g_rank[e] = atomicAdd(&g_deg[d], 1);
}

__global__ void __launch_bounds__(1024) scan_blocks() {
    __shared__ int sh[1024];
    int t = threadIdx.x;
    unsigned i = blockIdx.x * 1024u + t;
    int v = (i <= N_NODES) ? g_deg[i] : 0;
    sh[t] = v; __syncthreads();
#pragma unroll
    for (int off = 1; off < 1024; off <<= 1) {
        int add = (t >= off) ? sh[t - off] : 0;
        __syncthreads();
        sh[t] += add;
        __syncthreads();
    }
    if (i <= N_NODES) g_off[i] = sh[t] - v;
    if (t == 1023) g_bsum[blockIdx.x] = sh[t];
}

__global__ void __launch_bounds__(256) fixup_offsets() {
    __shared__ int sb[128];
    int t = threadIdx.x;
    if (t < 128) sb[t] = (t < NB_SCAN) ? g_bsum[t] : 0;
    __syncthreads();
#pragma unroll
    for (int off = 1; off < 128; off <<= 1) {
        int add = (t < 128 && t >= off) ? sb[t - off] : 0;
        __syncthreads();
        if (t < 128) sb[t] += add;
        __syncthreads();
    }
    unsigned i = blockIdx.x * 256u + t;
    if (i > N_NODES) return;
    unsigned b = i >> 10;
    int pre = (b == 0) ? 0 : sb[b - 1];       // exclusive
    g_off[i] = g_off[i] + pre;
    g_deg[i] = 0;                             // self-clean for next call
}

// ---------------- scatter (atomic-free: rank precomputed) --------------------
__global__ void scatter_csr(const void* __restrict__ ei) {
    unsigned e = blockIdx.x * 256u + threadIdx.x;
    if (e >= (unsigned)TOT_E) return;
    int s, d;
    if (e < (unsigned)N_EDGES) {
        if (g_is64) {
            const long long* p = (const long long*)ei;
            s = (int)p[e]; d = (int)p[N_EDGES + e];
        } else {
            const int* p = (const int*)ei;
            s = p[e]; d = p[N_EDGES + e];
        }
    } else {
        s = d = (int)(e - (unsigned)N_EDGES);
    }
    g_csr_src[g_off[d] + g_rank[e]] = s;
}

// ---------------- layer 1 GEMM: 8 nodes/warp, f32x2 accumulation -------------
__global__ void __launch_bounds__(256) gemm1(const float* __restrict__ x,
                                             const float* __restrict__ W,
                                             const float* __restrict__ asrc,
                                             const float* __restrict__ adst) {
    __shared__ float Ws[F_IN * HC];           // 32 KB
    __shared__ float xs[8][F_IN * 8];         // 32 KB: [warp][k*8 + node]
    __shared__ float as_s[HC], ad_s[HC];

    int tid = threadIdx.x;
    for (int i = tid; i < F_IN * HC; i += 256) Ws[i] = W[i];
    if (tid < HC) { as_s[tid] = asrc[tid]; ad_s[tid] = adst[tid]; }

    int warp = tid >> 5, lane = tid & 31;
    int n0 = blockIdx.x * 64 + warp * 8;

#pragma unroll
    for (int u = 0; u < 8; u++) {
        int n = n0 + u; if (n >= N_NODES) n = N_NODES - 1;
        const float* xr = x + (size_t)n * F_IN;
#pragma unroll
        for (int c = 0; c < 4; c++) {
            int k = lane + c * 32;
            xs[warp][k * 8 + u] = xr[k];
        }
    }
    __syncthreads();

    const float2* W2p = (const float2*)Ws;
    u64 acc[8];
#pragma unroll
    for (int u = 0; u < 8; u++) acc[u] = 0;

#pragma unroll 4
    for (int k = 0; k < F_IN; k++) {
        float4 xa = *(const float4*)&xs[warp][k * 8];
        float4 xb = *(const float4*)&xs[warp][k * 8 + 4];
        float2 wv = W2p[k * 32 + lane];
        u64 wp = pack2(wv.x, wv.y);
        fma2(acc[0], pack2(xa.x, xa.x), wp);
        fma2(acc[1], pack2(xa.y, xa.y), wp);
        fma2(acc[2], pack2(xa.z, xa.z), wp);
        fma2(acc[3], pack2(xa.w, xa.w), wp);
        fma2(acc[4], pack2(xb.x, xb.x), wp);
        fma2(acc[5], pack2(xb.y, xb.y), wp);
        fma2(acc[6], pack2(xb.z, xb.z), wp);
        fma2(acc[7], pack2(xb.w, xb.w), wp);
    }

    int j0 = lane * 2;
    float asx = as_s[j0], asy = as_s[j0 + 1];
    float adx = ad_s[j0], ady = ad_s[j0 + 1];

#pragma unroll
    for (int u = 0; u < 8; u++) {
        int n = n0 + u;
        float2 f = unpack2(acc[u]);
        float A0 = f.x, A1 = f.y;
        float ps = A0 * asx + A1 * asy;
        float pd = A0 * adx + A1 * ady;
        ps += __shfl_xor_sync(0xffffffffu, ps, 1);
        ps += __shfl_xor_sync(0xffffffffu, ps, 2);
        pd += __shfl_xor_sync(0xffffffffu, pd, 1);
        pd += __shfl_xor_sync(0xffffffffu, pd, 2);
        if (n < N_NODES) {
            g_h1h[n * 32 + lane] = __floats2half2_rn(A0, A1);
            if ((lane & 3) == 0) {
                int hh = lane >> 2;
                g_e1[n * HEADS + hh] = __floats2half2_rn(__expf(ps), __expf(0.2f * ps));
                g_ad1[n * HEADS + hh] = pd;
            }
        }
    }
}

// ---------------- layer 1 aggregation (direct csr loads) + fused gemm2 ------
// Warp per node. Lane = slot p=lane>>3 x head q=lane&7. Lane loads its own
// csr entry (8-lane broadcast) — no shfl, no batch bookkeeping. Unroll 4.
__global__ void __launch_bounds__(256) edge1_fused(const float* __restrict__ b1,
                                                   const float* __restrict__ W2,
                                                   const float* __restrict__ as2v,
                                                   const float* __restrict__ ad2v) {
    __shared__ float Ws2[HC * NCLS];          // 10 KB
    __shared__ float a2s[NCLS], a2d[NCLS];
    __shared__ float hs[8][HC];

    int tid = threadIdx.x;
    for (int i = tid; i < HC * NCLS; i += 256) Ws2[i] = W2[i];
    if (tid < NCLS) { a2s[tid] = as2v[tid]; a2d[tid] = ad2v[tid]; }
    __syncthreads();

    int warp = tid >> 5, lane = tid & 31;
    int n = blockIdx.x * 8 + warp;
    if (n >= N_NODES) return;
    int q = lane & 7;                          // head
    int p = lane >> 3;                         // edge slot 0..3

    float ad  = g_ad1[n * 8 + q];
    float epd = __expf(ad);
    float emd = __expf(0.2f * ad);
    float den = 0.f;
    float a0 = 0.f, a1 = 0.f, a2 = 0.f, a3 = 0.f,
          a4 = 0.f, a5 = 0.f, a6 = 0.f, a7 = 0.f;

#define ACCUM(E, H)                                                              \
    {                                                                            \
        float2 v0 = __half22float2(*(__half2*)&(H).x);                           \
        float2 v1 = __half22float2(*(__half2*)&(H).y);                           \
        float2 v2 = __half22float2(*(__half2*)&(H).z);                           \
        float2 v3 = __half22float2(*(__half2*)&(H).w);                           \
        a0 += (E) * v0.x; a1 += (E) * v0.y; a2 += (E) * v1.x; a3 += (E) * v1.y;  \
        a4 += (E) * v2.x; a5 += (E) * v2.y; a6 += (E) * v3.x; a7 += (E) * v3.y;  \
    }
#define EDGE1(S)                                                                 \
    {                                                                            \
        __half2 es = g_e1[(S) * 8 + q];                                          \
        uint4 h = *(const uint4*)(g_h1h + (S) * 32 + q * 4);                     \
        float2 ef = __half22float2(es);                                          \
        float pe = ef.x * epd;                                                   \
        float e = pe > 1.f ? pe : ef.y * emd;                                    \
        den += e;                                                                \
        ACCUM(e, h)                                                              \
    }

    int k = g_off[n] + p;
    int end = g_off[n + 1];
    for (; k + 12 < end; k += 16) {           // 4 edges per lane per iter
        int s0 = g_csr_src[k];
        int s1 = g_csr_src[k + 4];
        int s2 = g_csr_src[k + 8];
        int s3 = g_csr_src[k + 12];
        EDGE1(s0) EDGE1(s1) EDGE1(s2) EDGE1(s3)
    }
    for (; k < end; k += 4) {
        int s = g_csr_src[k];
        EDGE1(s)
    }
#undef EDGE1
#undef ACCUM

#define RED(X) X += __shfl_xor_sync(0xffffffffu, X, 8); X += __shfl_xor_sync(0xffffffffu, X, 16);
    RED(den) RED(a0) RED(a1) RED(a2) RED(a3) RED(a4) RED(a5) RED(a6) RED(a7)
#undef RED

    if (p == 0) {
        int c0 = q * 8;
        float4 ba = *(const float4*)(b1 + c0);
        float4 bb = *(const float4*)(b1 + c0 + 4);
        float inv = 1.f / (den + 1e-16f);
        hs[warp][c0]     = fmaxf(a0 * inv + ba.x, 0.f);
        hs[warp][c0 + 1] = fmaxf(a1 * inv + ba.y, 0.f);
        hs[warp][c0 + 2] = fmaxf(a2 * inv + ba.z, 0.f);
        hs[warp][c0 + 3] = fmaxf(a3 * inv + ba.w, 0.f);
        hs[warp][c0 + 4] = fmaxf(a4 * inv + bb.x, 0.f);
        hs[warp][c0 + 5] = fmaxf(a5 * inv + bb.y, 0.f);
        hs[warp][c0 + 6] = fmaxf(a6 * inv + bb.z, 0.f);
        hs[warp][c0 + 7] = fmaxf(a7 * inv + bb.w, 0.f);
    }
    __syncwarp();

    // ---- fused layer-2 GEMM ----
    float acc0 = 0.f, acc1 = 0.f;
    int l8 = 32 + (lane & 7);
#pragma unroll 8
    for (int w = 0; w < HC; w++) {
        float hv = hs[warp][w];
        acc0 += hv * Ws2[w * NCLS + lane];
        acc1 += hv * Ws2[w * NCLS + l8];
    }

    __half* h2p = (__half*)g_h2h;
    h2p[n * NCLS + lane] = __float2half_rn(acc0);
    if (lane < 8) h2p[n * NCLS + 32 + lane] = __float2half_rn(acc1);

    float ps = acc0 * a2s[lane] + (lane < 8 ? acc1 * a2s[32 + lane] : 0.f);
    float pd = acc0 * a2d[lane] + (lane < 8 ? acc1 * a2d[32 + lane] : 0.f);
#pragma unroll
    for (int o = 16; o; o >>= 1) {
        ps += __shfl_xor_sync(0xffffffffu, ps, o);
        pd += __shfl_xor_sync(0xffffffffu, pd, o);
    }
    if (lane == 0) {
        g_e2[n] = __floats2half2_rn(__expf(ps), __expf(0.2f * ps));
        g_ad2[n] = pd;
    }
}

// ---------------- layer 2 CSR aggregation (direct csr loads) -----------------
// 6 groups of 5 lanes; lane t owns classes [8t,8t+8). Group g loads its own
// csr entries with stride 6; lanes 30,31 idle through the loop.
__global__ void __launch_bounds__(256) edge_csr2(float* __restrict__ out,
                                                 const float* __restrict__ b2) {
    int warp = (blockIdx.x * 256 + threadIdx.x) >> 5;
    int lane = threadIdx.x & 31;
    if (warp >= N_NODES) return;
    int n = warp;
    int g = lane / 5;
    int t = lane - g * 5;
    bool live = g < 6;
    int ti = live ? t : 0;

    float ad  = g_ad2[n];
    float epd = __expf(ad);
    float emd = __expf(0.2f * ad);
    float den = 0.f;
    float a0 = 0.f, a1 = 0.f, a2 = 0.f, a3 = 0.f,
          a4 = 0.f, a5 = 0.f, a6 = 0.f, a7 = 0.f;

#define ACCUM(E, H)                                                              \
    {                                                                            \
        float2 v0 = __half22float2(*(__half2*)&(H).x);                           \
        float2 v1 = __half22float2(*(__half2*)&(H).y);                           \
        float2 v2 = __half22float2(*(__half2*)&(H).z);                           \
        float2 v3 = __half22float2(*(__half2*)&(H).w);                           \
        a0 += (E) * v0.x; a1 += (E) * v0.y; a2 += (E) * v1.x; a3 += (E) * v1.y;  \
        a4 += (E) * v2.x; a5 += (E) * v2.y; a6 += (E) * v3.x; a7 += (E) * v3.y;  \
    }
#define EDGE2(S)                                                                 \
    {                                                                            \
        __half2 es = g_e2[(S)];                                                  \
        uint4 h = *(const uint4*)((const uint4*)g_h2h + (S) * 5 + ti);           \
        float2 ef = __half22float2(es);                                          \
        float pe = ef.x * epd;                                                   \
        float e = pe > 1.f ? pe : ef.y * emd;                                    \
        den += e;                                                                \
        ACCUM(e, h)                                                              \
    }

    int k = g_off[n] + g;
    int end = live ? g_off[n + 1] : 0;
    if (!live) k = 0;
    for (; k + 6 < end; k += 12) {            // 2 edges per group per iter
        int s0 = g_csr_src[k];
        int s1 = g_csr_src[k + 6];
        EDGE2(s0) EDGE2(s1)
    }
    for (; k < end; k += 6) {
        int s = g_csr_src[k];
        EDGE2(s)
    }
#undef EDGE2
#undef ACCUM

#define RED(X)                                                                   \
    {                                                                            \
        float w = __shfl_sync(0xffffffffu, X, (lane + 15) & 31); X += w;         \
        float u = __shfl_sync(0xffffffffu, X, (lane + 5) & 31);                  \
        float v = __shfl_sync(0xffffffffu, X, (lane + 10) & 31);                 \
        X += u + v;                                                              \
    }
    RED(den) RED(a0) RED(a1) RED(a2) RED(a3) RED(a4) RED(a5) RED(a6) RED(a7)
#undef RED

    if (lane < 5) {
        int c0 = lane * 8;
        float4 ba = *(const float4*)(b2 + c0);
        float4 bb = *(const float4*)(b2 + c0 + 4);
        float inv = 1.f / (den + 1e-16f);
        float4 r0, r1;
        r0.x = a0 * inv + ba.x; r0.y = a1 * inv + ba.y;
        r0.z = a2 * inv + ba.z; r0.w = a3 * inv + ba.w;
        r1.x = a4 * inv + bb.x; r1.y = a5 * inv + bb.y;
        r1.z = a6 * inv + bb.z; r1.w = a7 * inv + bb.w;
        *(float4*)(out + n * NCLS + c0)     = r0;
        *(float4*)(out + n * NCLS + c0 + 4) = r1;
    }
}

// ---------------- launch -----------------------------------------------------
extern "C" void kernel_launch(void* const* d_in, const int* in_sizes, int n_in,
                              void* d_out, int out_size) {
    const float* x   = (const float*)d_in[0];
    const void*  ei  = d_in[1];
    const float* W1  = (const float*)d_in[2];
    const float* as1 = (const float*)d_in[3];
    const float* ad1 = (const float*)d_in[4];
    const float* b1  = (const float*)d_in[5];
    const float* W2  = (const float*)d_in[6];
    const float* as2 = (const float*)d_in[7];
    const float* ad2 = (const float*)d_in[8];
    const float* b2  = (const float*)d_in[9];
    float*       out = (float*)d_out;

    // fork: CSR build on side stream, gemm1 concurrently on main stream
    cudaStream_t s1;
    cudaStreamCreateWithFlags(&s1, cudaStreamNonBlocking);
    cudaEvent_t ev0, ev1;
    cudaEventCreateWithFlags(&ev0, cudaEventDisableTiming);
    cudaEventCreateWithFlags(&ev1, cudaEventDisableTiming);

    cudaEventRecord(ev0, 0);
    cudaStreamWaitEvent(s1, ev0, 0);

    // ---- CSR build (side stream): 4 kernels ----
    hist_dst<<<((unsigned)TOT_E + 255) / 256, 256, 0, s1>>>(ei);
    scan_blocks<<<NB_SCAN, 1024, 0, s1>>>();
    fixup_offsets<<<(N_NODES + 256) / 256, 256, 0, s1>>>();
    scatter_csr<<<((unsigned)TOT_E + 255) / 256, 256, 0, s1>>>(ei);
    cudaEventRecord(ev1, s1);

    // ---- layer 1 GEMM (main stream, overlapped) ----
    gemm1<<<(N_NODES + 63) / 64, 256>>>(x, W1, as1, ad1);

    // join
    cudaStreamWaitEvent(0, ev1, 0);

    // ---- layer 1 aggregation + fused layer-2 GEMM ----
    edge1_fused<<<(N_NODES + 7) / 8, 256>>>(b1, W2, as2, ad2);

    // ---- layer 2 ----
    edge_csr2<<<(N_NODES * 32 + 255) / 256, 256>>>(out, b2);

    cudaEventDestroy(ev0);
    cudaEventDestroy(ev1);
    cudaStreamDestroy(s1);
}